// round 2
// baseline (speedup 1.0000x reference)
#include <cuda_runtime.h>

// YOLOLoss on GB300 — HBM-streaming reduction.
// Pass 1: 1 block = 128 cells; coalesced float4 staging to smem, per-cell math,
//         block-reduce -> per-block partial in __device__ scratch.
// Pass 2: single block, double-precision deterministic final reduce.

#define N_CLS 20
#define CELL_D 30          // 2*5 + 20 floats per cell
#define CPB 128            // cells per block
#define MAX_BLOCKS 32768

__device__ float g_partials[MAX_BLOCKS];

__device__ __forceinline__ float iou_pair(const float* p, const float* t) {
    float x1 = p[0], y1 = p[1], w1 = p[2], h1 = p[3];
    float x2 = t[0], y2 = t[1], w2 = t[2], h2 = t[3];
    float iw = fmaxf(0.0f, fminf(fmaf(0.5f, w1, x1), fmaf(0.5f, w2, x2))
                         - fmaxf(fmaf(-0.5f, w1, x1), fmaf(-0.5f, w2, x2)));
    float ih = fmaxf(0.0f, fminf(fmaf(0.5f, h1, y1), fmaf(0.5f, h2, y2))
                         - fmaxf(fmaf(-0.5f, h1, y1), fmaf(-0.5f, h2, y2)));
    float inter = iw * ih;
    float uni   = w1 * h1 + w2 * h2 - inter;
    return inter / (uni + 1e-10f);
}

__global__ void __launch_bounds__(CPB)
yolo_cell_kernel(const float* __restrict__ preds,
                 const float* __restrict__ targets,
                 long long nCells)
{
    __shared__ float sp[CPB * CELL_D];
    __shared__ float st[CPB * CELL_D];

    const int tid = threadIdx.x;
    const long long blockBase = (long long)blockIdx.x * CPB;
    const long long elemBase  = blockBase * CELL_D;
    const int cellsHere = (int)min((long long)CPB, nCells - blockBase);
    const int nFloats   = cellsHere * CELL_D;

    // --- Coalesced staging (float4; block base = 15360 B -> 16B aligned) ---
    const float4* __restrict__ p4 = reinterpret_cast<const float4*>(preds + elemBase);
    const float4* __restrict__ t4 = reinterpret_cast<const float4*>(targets + elemBase);
    const int nVec = nFloats >> 2;
    #pragma unroll 4
    for (int i = tid; i < nVec; i += CPB) {
        reinterpret_cast<float4*>(sp)[i] = p4[i];
        reinterpret_cast<float4*>(st)[i] = t4[i];
    }
    if (nFloats & 3) {          // never taken for full blocks (3840 % 4 == 0)
        for (int i = (nVec << 2) + tid; i < nFloats; i += CPB) {
            sp[i] = preds[elemBase + i];
            st[i] = targets[elemBase + i];
        }
    }
    __syncthreads();

    // --- Per-cell loss ---
    float loss = 0.0f;
    if (tid < cellsHere) {
        const float* p = sp + tid * CELL_D;
        const float* t = st + tid * CELL_D;

        float iou0 = iou_pair(p, t);
        float iou1 = iou_pair(p + 5, t + 5);
        // jnp.argmax: first max -> index 1 only on strict >
        int bsel = (iou1 > iou0) ? 1 : 0;

        // coordinate loss (masked by has_obj = targets[...,4] > 0)
        if (t[4] > 0.0f) {
            float dx = p[bsel * 5 + 0] - t[bsel * 5 + 0];
            float dy = p[bsel * 5 + 1] - t[bsel * 5 + 1];
            loss += dx * dx + dy * dy;
        }

        // class SSE + gt-class argmax (first max on ties)
        float tcmax = t[10];
        int gt = 0;
        #pragma unroll
        for (int c = 0; c < N_CLS; c++) {
            float pc = p[10 + c];
            float tc = t[10 + c];
            float d  = pc - tc;
            loss = fmaf(d, d, loss);
            if (c > 0 && tc > tcmax) { tcmax = tc; gt = c; }
        }

        // confidence loss: sum_b w_b * iou_b^2 * (pc_gt - 1)^2
        float e  = p[10 + gt] - 1.0f;
        float e2 = e * e;
        float w0 = (bsel == 0) ? 1.0f : 0.5f;
        float w1 = (bsel == 1) ? 1.0f : 0.5f;
        loss = fmaf(w0 * iou0 * iou0 + w1 * iou1 * iou1, e2, loss);
    }

    // --- Block reduction ---
    #pragma unroll
    for (int off = 16; off > 0; off >>= 1)
        loss += __shfl_down_sync(0xffffffffu, loss, off);

    __shared__ float warpsum[CPB / 32];
    if ((tid & 31) == 0) warpsum[tid >> 5] = loss;
    __syncthreads();

    if (tid < 32) {
        float v = (tid < CPB / 32) ? warpsum[tid] : 0.0f;
        #pragma unroll
        for (int off = (CPB / 64); off > 0; off >>= 1)
            v += __shfl_down_sync(0xffffffffu, v, off);
        if (tid == 0) g_partials[blockIdx.x] = v;
    }
}

__global__ void yolo_final_kernel(float* __restrict__ out, int nBlocks, double invN)
{
    const int tid = threadIdx.x;
    double acc = 0.0;
    for (int i = tid; i < nBlocks; i += blockDim.x)
        acc += (double)g_partials[i];

    #pragma unroll
    for (int off = 16; off > 0; off >>= 1)
        acc += __shfl_down_sync(0xffffffffu, acc, off);

    __shared__ double ws[8];
    if ((tid & 31) == 0) ws[tid >> 5] = acc;
    __syncthreads();

    if (tid < 32) {
        double v = (tid < 8) ? ws[tid] : 0.0;
        #pragma unroll
        for (int off = 4; off > 0; off >>= 1)
            v += __shfl_down_sync(0xffffffffu, v, off);
        if (tid == 0) out[0] = (float)(v * invN);
    }
}

extern "C" void kernel_launch(void* const* d_in, const int* in_sizes, int n_in,
                              void* d_out, int out_size)
{
    const float* preds   = (const float*)d_in[0];
    const float* targets = (const float*)d_in[1];

    long long total  = (long long)in_sizes[0];     // N*S*S*30
    long long nCells = total / CELL_D;             // N*S*S
    long long N      = nCells / 49;                // S = 7
    int nBlocks      = (int)((nCells + CPB - 1) / CPB);
    if (nBlocks > MAX_BLOCKS) nBlocks = MAX_BLOCKS; // shape-guard (not hit at this size)

    yolo_cell_kernel<<<nBlocks, CPB>>>(preds, targets, nCells);
    yolo_final_kernel<<<1, 256>>>((float*)d_out, nBlocks, 1.0 / (double)N);
}

// round 10
// speedup vs baseline: 1.2414x; 1.2414x over previous
#include <cuda_runtime.h>

// YOLOLoss on GB300 — single-kernel HBM-streaming reduction.
// Persistent grid; 1 tile = 128 cells staged via coalesced float4 -> smem.
// Deterministic fixed-point (x 2^24) int64 atomic accumulation; the last
// block to finish writes the final scaled result and resets the globals.

#define N_CLS   20
#define CELL_D  30          // 2*5 + 20 floats per cell
#define CPB     128         // cells per tile (== threads per block)
#define SCALE   16777216.0  // 2^24
#define INV_SCALE (1.0 / 16777216.0)

__device__ unsigned long long g_acc  = 0ull;
__device__ unsigned int       g_done = 0u;

__device__ __forceinline__ float iou_pair(const float* p, const float* t) {
    float x1 = p[0], y1 = p[1], w1 = p[2], h1 = p[3];
    float x2 = t[0], y2 = t[1], w2 = t[2], h2 = t[3];
    float iw = fmaxf(0.0f, fminf(fmaf(0.5f, w1, x1), fmaf(0.5f, w2, x2))
                         - fmaxf(fmaf(-0.5f, w1, x1), fmaf(-0.5f, w2, x2)));
    float ih = fmaxf(0.0f, fminf(fmaf(0.5f, h1, y1), fmaf(0.5f, h2, y2))
                         - fmaxf(fmaf(-0.5f, h1, y1), fmaf(-0.5f, h2, y2)));
    float inter = iw * ih;
    float uni   = w1 * h1 + w2 * h2 - inter;
    return inter / (uni + 1e-10f);
}

__global__ void __launch_bounds__(CPB)
yolo_loss_kernel(const float* __restrict__ preds,
                 const float* __restrict__ targets,
                 long long nCells, int nTiles,
                 float* __restrict__ out, double invN)
{
    __shared__ float sp[CPB * CELL_D];
    __shared__ float st[CPB * CELL_D];

    const int tid = threadIdx.x;
    float threadLoss = 0.0f;   // accumulated across tiles

    bool first = true;
    for (int tile = blockIdx.x; tile < nTiles; tile += gridDim.x) {
        const long long blockBase = (long long)tile * CPB;
        const long long elemBase  = blockBase * CELL_D;
        const int cellsHere = (int)min((long long)CPB, nCells - blockBase);
        const int nFloats   = cellsHere * CELL_D;

        if (!first) __syncthreads();   // protect smem reuse across iterations
        first = false;

        // --- Coalesced staging (float4; tile base = 15360 B -> 16B aligned) ---
        const float4* __restrict__ p4 = reinterpret_cast<const float4*>(preds + elemBase);
        const float4* __restrict__ t4 = reinterpret_cast<const float4*>(targets + elemBase);
        const int nVec = nFloats >> 2;
        #pragma unroll 4
        for (int i = tid; i < nVec; i += CPB) {
            reinterpret_cast<float4*>(sp)[i] = p4[i];
            reinterpret_cast<float4*>(st)[i] = t4[i];
        }
        if (nFloats & 3) {  // never taken for full tiles (3840 % 4 == 0)
            for (int i = (nVec << 2) + tid; i < nFloats; i += CPB) {
                sp[i] = preds[elemBase + i];
                st[i] = targets[elemBase + i];
            }
        }
        __syncthreads();

        // --- Per-cell loss ---
        if (tid < cellsHere) {
            const float* p = sp + tid * CELL_D;
            const float* t = st + tid * CELL_D;

            float iou0 = iou_pair(p, t);
            float iou1 = iou_pair(p + 5, t + 5);
            int bsel = (iou1 > iou0) ? 1 : 0;   // jnp.argmax: first max wins ties

            float loss = 0.0f;

            // coordinate loss (masked by has_obj = targets[...,4] > 0)
            if (t[4] > 0.0f) {
                float dx = p[bsel * 5 + 0] - t[bsel * 5 + 0];
                float dy = p[bsel * 5 + 1] - t[bsel * 5 + 1];
                loss += dx * dx + dy * dy;
            }

            // class SSE + gt-class argmax (first max on ties)
            float tcmax = t[10];
            int gt = 0;
            #pragma unroll
            for (int c = 0; c < N_CLS; c++) {
                float pc = p[10 + c];
                float tc = t[10 + c];
                float d  = pc - tc;
                loss = fmaf(d, d, loss);
                if (c > 0 && tc > tcmax) { tcmax = tc; gt = c; }
            }

            // confidence loss: sum_b w_b * iou_b^2 * (pc_gt - 1)^2
            float e  = p[10 + gt] - 1.0f;
            float e2 = e * e;
            float w0 = (bsel == 0) ? 1.0f : 0.5f;
            float w1 = (bsel == 1) ? 1.0f : 0.5f;
            loss = fmaf(w0 * iou0 * iou0 + w1 * iou1 * iou1, e2, loss);

            threadLoss += loss;
        }
    }

    // --- Block reduction of per-thread accumulators ---
    float blockLoss = threadLoss;
    #pragma unroll
    for (int off = 16; off > 0; off >>= 1)
        blockLoss += __shfl_down_sync(0xffffffffu, blockLoss, off);

    __shared__ float warpsum[CPB / 32];
    if ((tid & 31) == 0) warpsum[tid >> 5] = blockLoss;
    __syncthreads();

    bool amLast = false;
    if (tid < 32) {
        float v = (tid < CPB / 32) ? warpsum[tid] : 0.0f;
        #pragma unroll
        for (int off = (CPB / 64); off > 0; off >>= 1)
            v += __shfl_down_sync(0xffffffffu, v, off);
        if (tid == 0) {
            // deterministic fixed-point accumulate (integer add is associative)
            unsigned long long q =
                (unsigned long long)((double)v * SCALE + 0.5);
            atomicAdd(&g_acc, q);
            __threadfence();
            unsigned int prev = atomicAdd(&g_done, 1u);
            amLast = (prev == (unsigned int)gridDim.x - 1u);
        }
    }

    // last block's thread 0: finalize + reset globals for next graph replay
    if (amLast) {
        unsigned long long total = g_acc;
        out[0] = (float)((double)total * INV_SCALE * invN);
        g_acc  = 0ull;
        g_done = 0u;
    }
}

extern "C" void kernel_launch(void* const* d_in, const int* in_sizes, int n_in,
                              void* d_out, int out_size)
{
    const float* preds   = (const float*)d_in[0];
    const float* targets = (const float*)d_in[1];

    long long total  = (long long)in_sizes[0];     // N*S*S*30
    long long nCells = total / CELL_D;             // N*S*S
    long long N      = nCells / 49;                // S = 7
    int nTiles       = (int)((nCells + CPB - 1) / CPB);

    int grid = 148 * 7;                            // persistent: 7 CTAs/SM
    if (grid > nTiles) grid = nTiles;

    yolo_loss_kernel<<<grid, CPB>>>(preds, targets, nCells, nTiles,
                                    (float*)d_out, 1.0 / (double)N);
}

// round 16
// speedup vs baseline: 1.4094x; 1.1353x over previous
#include <cuda_runtime.h>
#include <cstdint>

// YOLOLoss on GB300 — single-kernel HBM-streaming reduction with a
// cp.async double-buffered pipeline: stage tile k+1 while computing tile k.
// Deterministic fixed-point (x 2^24) int64 atomic accumulation; the last
// block to finish writes the final scaled result and resets the globals.

#define N_CLS   20
#define CELL_D  30                    // 2*5 + 20 floats per cell
#define CPB     128                   // cells per tile (== threads per block)
#define TILE_FLOATS (CPB * CELL_D)    // 3840 floats per array per tile
#define TILE_VEC    (TILE_FLOATS / 4) // 960 float4 per array per tile
#define BUF_FLOATS  (2 * TILE_FLOATS) // sp + st per buffer
#define SMEM_FLOATS (2 * BUF_FLOATS)  // double buffer -> 15360 floats = 61440 B
#define SCALE   16777216.0            // 2^24
#define INV_SCALE (1.0 / 16777216.0)

__device__ unsigned long long g_acc  = 0ull;
__device__ unsigned int       g_done = 0u;

__device__ __forceinline__ void cp_async16(uint32_t saddr, const void* gptr) {
    asm volatile("cp.async.cg.shared.global [%0], [%1], 16;"
                 :: "r"(saddr), "l"(gptr));
}
__device__ __forceinline__ void cp_commit() {
    asm volatile("cp.async.commit_group;");
}
template <int N>
__device__ __forceinline__ void cp_wait() {
    asm volatile("cp.async.wait_group %0;" :: "n"(N));
}

__device__ __forceinline__ float iou_pair(const float* p, const float* t) {
    float x1 = p[0], y1 = p[1], w1 = p[2], h1 = p[3];
    float x2 = t[0], y2 = t[1], w2 = t[2], h2 = t[3];
    float iw = fmaxf(0.0f, fminf(fmaf(0.5f, w1, x1), fmaf(0.5f, w2, x2))
                         - fmaxf(fmaf(-0.5f, w1, x1), fmaf(-0.5f, w2, x2)));
    float ih = fmaxf(0.0f, fminf(fmaf(0.5f, h1, y1), fmaf(0.5f, h2, y2))
                         - fmaxf(fmaf(-0.5f, h1, y1), fmaf(-0.5f, h2, y2)));
    float inter = iw * ih;
    float uni   = w1 * h1 + w2 * h2 - inter;
    return inter / (uni + 1e-10f);
}

// Stage one tile (preds + targets) into one smem buffer using cp.async for
// the float4-aligned body; scalar tail (dead at this shape) uses plain STS.
__device__ __forceinline__ void stage_tile(float* sbuf, uint32_t sbuf_s,
                                           const float* __restrict__ preds,
                                           const float* __restrict__ targets,
                                           long long elemBase, int nFloats, int tid)
{
    const float4* __restrict__ p4 = reinterpret_cast<const float4*>(preds + elemBase);
    const float4* __restrict__ t4 = reinterpret_cast<const float4*>(targets + elemBase);
    const int nVec = nFloats >> 2;
    #pragma unroll 4
    for (int i = tid; i < nVec; i += CPB) {
        cp_async16(sbuf_s + (uint32_t)i * 16u, p4 + i);
        cp_async16(sbuf_s + (uint32_t)(TILE_FLOATS / 4 + i) * 16u, t4 + i);
    }
    if (nFloats & 3) {  // never taken for full tiles (3840 % 4 == 0)
        for (int i = (nVec << 2) + tid; i < nFloats; i += CPB) {
            sbuf[i]               = preds[elemBase + i];
            sbuf[TILE_FLOATS + i] = targets[elemBase + i];
        }
    }
}

__global__ void __launch_bounds__(CPB)
yolo_loss_kernel(const float* __restrict__ preds,
                 const float* __restrict__ targets,
                 long long nCells, int nTiles,
                 float* __restrict__ out, double invN)
{
    extern __shared__ float smem[];   // [2][2][TILE_FLOATS]
    const uint32_t smem_s = (uint32_t)__cvta_generic_to_shared(smem);

    const int tid = threadIdx.x;
    float threadLoss = 0.0f;

    const int firstTile = blockIdx.x;
    const int stride    = gridDim.x;

    if (firstTile < nTiles) {
        // --- Prologue: stage first tile into buffer 0 ---
        {
            const long long bb = (long long)firstTile * CPB;
            const int ch = (int)min((long long)CPB, nCells - bb);
            stage_tile(smem, smem_s, preds, targets, bb * CELL_D, ch * CELL_D, tid);
            cp_commit();
        }

        int cur = 0;
        for (int tile = firstTile; tile < nTiles; tile += stride) {
            const int  nextTile = tile + stride;
            const bool hasNext  = nextTile < nTiles;

            // --- Stage next tile into the other buffer while current loads land ---
            if (hasNext) {
                const long long bb = (long long)nextTile * CPB;
                const int ch = (int)min((long long)CPB, nCells - bb);
                float*   nb   = smem  + (cur ^ 1) * BUF_FLOATS;
                uint32_t nb_s = smem_s + (uint32_t)((cur ^ 1) * BUF_FLOATS) * 4u;
                stage_tile(nb, nb_s, preds, targets, bb * CELL_D, ch * CELL_D, tid);
                cp_commit();
                cp_wait<1>();   // current tile's group complete; next in flight
            } else {
                cp_wait<0>();   // drain everything
            }
            __syncthreads();

            // --- Per-cell loss on current buffer ---
            const long long blockBase = (long long)tile * CPB;
            const int cellsHere = (int)min((long long)CPB, nCells - blockBase);
            if (tid < cellsHere) {
                const float* p = smem + cur * BUF_FLOATS + tid * CELL_D;
                const float* t = p + TILE_FLOATS;

                float iou0 = iou_pair(p, t);
                float iou1 = iou_pair(p + 5, t + 5);
                int bsel = (iou1 > iou0) ? 1 : 0;   // jnp.argmax: first max wins

                float loss = 0.0f;

                // coordinate loss (masked by has_obj = targets[...,4] > 0)
                if (t[4] > 0.0f) {
                    float dx = p[bsel * 5 + 0] - t[bsel * 5 + 0];
                    float dy = p[bsel * 5 + 1] - t[bsel * 5 + 1];
                    loss += dx * dx + dy * dy;
                }

                // class SSE + gt-class argmax (first max on ties)
                float tcmax = t[10];
                int gt = 0;
                #pragma unroll
                for (int c = 0; c < N_CLS; c++) {
                    float pc = p[10 + c];
                    float tc = t[10 + c];
                    float d  = pc - tc;
                    loss = fmaf(d, d, loss);
                    if (c > 0 && tc > tcmax) { tcmax = tc; gt = c; }
                }

                // confidence loss: sum_b w_b * iou_b^2 * (pc_gt - 1)^2
                float e  = p[10 + gt] - 1.0f;
                float e2 = e * e;
                float w0 = (bsel == 0) ? 1.0f : 0.5f;
                float w1 = (bsel == 1) ? 1.0f : 0.5f;
                loss = fmaf(w0 * iou0 * iou0 + w1 * iou1 * iou1, e2, loss);

                threadLoss += loss;
            }

            __syncthreads();   // all reads of buf[cur] done before it's re-staged
            cur ^= 1;
        }
    }

    // --- Block reduction of per-thread accumulators ---
    float blockLoss = threadLoss;
    #pragma unroll
    for (int off = 16; off > 0; off >>= 1)
        blockLoss += __shfl_down_sync(0xffffffffu, blockLoss, off);

    __shared__ float warpsum[CPB / 32];
    if ((tid & 31) == 0) warpsum[tid >> 5] = blockLoss;
    __syncthreads();

    bool amLast = false;
    if (tid < 32) {
        float v = (tid < CPB / 32) ? warpsum[tid] : 0.0f;
        #pragma unroll
        for (int off = (CPB / 64); off > 0; off >>= 1)
            v += __shfl_down_sync(0xffffffffu, v, off);
        if (tid == 0) {
            // deterministic fixed-point accumulate (integer add is associative)
            unsigned long long q =
                (unsigned long long)((double)v * SCALE + 0.5);
            atomicAdd(&g_acc, q);
            __threadfence();
            unsigned int prev = atomicAdd(&g_done, 1u);
            amLast = (prev == (unsigned int)gridDim.x - 1u);
        }
    }

    // last block's thread 0: finalize + reset globals for next graph replay
    if (amLast) {
        unsigned long long total = g_acc;
        out[0] = (float)((double)total * INV_SCALE * invN);
        g_acc  = 0ull;
        g_done = 0u;
    }
}

extern "C" void kernel_launch(void* const* d_in, const int* in_sizes, int n_in,
                              void* d_out, int out_size)
{
    const float* preds   = (const float*)d_in[0];
    const float* targets = (const float*)d_in[1];

    long long total  = (long long)in_sizes[0];     // N*S*S*30
    long long nCells = total / CELL_D;             // N*S*S
    long long N      = nCells / 49;                // S = 7
    int nTiles       = (int)((nCells + CPB - 1) / CPB);

    int grid = 148 * 3;                            // 3 CTAs/SM (61.4 KB smem each)
    if (grid > nTiles) grid = nTiles;

    const size_t smemBytes = SMEM_FLOATS * sizeof(float);   // 61440
    cudaFuncSetAttribute(yolo_loss_kernel,
                         cudaFuncAttributeMaxDynamicSharedMemorySize,
                         (int)smemBytes);

    yolo_loss_kernel<<<grid, CPB, smemBytes>>>(preds, targets, nCells, nTiles,
                                               (float*)d_out, 1.0 / (double)N);
}